// round 3
// baseline (speedup 1.0000x reference)
#include <cuda_runtime.h>
#include <cuda_bf16.h>
#include <math.h>

#define BATCH   2
#define SEQ     4096
#define DMODEL  1024
#define NTOK    (BATCH*SEQ)     /* 8192 */
#define NHEAD   16
#define NKV     4
#define DHEAD   64
#define NBKT    32              /* n_buckets = ceil(4096/128) */
#define BUCKET  128

/* ---------------- scratch (device globals; no allocation allowed) -------- */
__device__ float g_zg   [NTOK*2048];   /* z | gate            */
__device__ float g_zm   [NTOK*1024];   /* silu(conv)*silu(g)  */
__device__ float g_qk   [NTOK*2048];   /* qg | kg             */
__device__ float g_q    [NTOK*1024];   /* q (low-rank folded) */
__device__ float g_kraw [NTOK*256];
__device__ float g_khaar[NTOK*256];
__device__ float g_v    [NTOK*256];
__device__ float g_o    [NTOK*1024];   /* attention out       */
__device__ float g_qweff[1024*1024];
__device__ float g_kweff[1024*256];
__device__ float g_Mq   [64*64];
__device__ float g_Mkg  [64*64];
__device__ int   g_bucket[NTOK];
__device__ int   g_order [NTOK];

/* ---------------- tiled fp32 GEMM: C[M,N] = A[M,K] @ B[K,N] -------------- */
__global__ __launch_bounds__(256) void sgemm128(
    const float* __restrict__ A, const float* __restrict__ B,
    float* __restrict__ C, int K, int lda, int ldb, int ldc)
{
    __shared__ float As[8][128];
    __shared__ float Bs[8][128];
    int tid  = threadIdx.x;
    int brow = blockIdx.y * 128;
    int bcol = blockIdx.x * 128;
    int tx = tid & 15, ty = tid >> 4;

    int arow  = tid >> 1;          /* 0..127 */
    int acol  = (tid & 1) * 4;     /* 0 or 4 */
    int bkrow = tid >> 5;          /* 0..7   */
    int bcol4 = (tid & 31) * 4;    /* 0..124 */

    const float* Ap = A + (size_t)(brow + arow) * lda + acol;
    const float* Bp = B + (size_t)bkrow * ldb + bcol + bcol4;

    float acc[8][8];
    #pragma unroll
    for (int i = 0; i < 8; i++)
        #pragma unroll
        for (int j = 0; j < 8; j++) acc[i][j] = 0.f;

    for (int k0 = 0; k0 < K; k0 += 8) {
        float4 a  = *(const float4*)(Ap + k0);
        float4 bv = *(const float4*)(Bp + (size_t)k0 * ldb);
        As[acol+0][arow] = a.x;
        As[acol+1][arow] = a.y;
        As[acol+2][arow] = a.z;
        As[acol+3][arow] = a.w;
        *(float4*)&Bs[bkrow][bcol4] = bv;
        __syncthreads();
        #pragma unroll
        for (int kk = 0; kk < 8; kk++) {
            float ar[8], br[8];
            #pragma unroll
            for (int i = 0; i < 8; i++) ar[i] = As[kk][ty*8+i];
            #pragma unroll
            for (int j = 0; j < 8; j++) br[j] = Bs[kk][tx*8+j];
            #pragma unroll
            for (int i = 0; i < 8; i++)
                #pragma unroll
                for (int j = 0; j < 8; j++) acc[i][j] += ar[i]*br[j];
        }
        __syncthreads();
    }
    #pragma unroll
    for (int i = 0; i < 8; i++) {
        float* Cp = C + (size_t)(brow + ty*8 + i) * ldc + bcol + tx*8;
        *(float4*)(Cp)   = make_float4(acc[i][0],acc[i][1],acc[i][2],acc[i][3]);
        *(float4*)(Cp+4) = make_float4(acc[i][4],acc[i][5],acc[i][6],acc[i][7]);
    }
}

/* -------- fold low-rank projections (+ tanh gate for k) into weights ----- */
__global__ void prep_M(const float* __restrict__ Aq, const float* __restrict__ Bq,
                       const float* __restrict__ Ak, const float* __restrict__ Bk,
                       const float* __restrict__ rand_gate)
{
    int i = blockIdx.x, j = threadIdx.x;   /* 64 x 64 */
    float sq = 0.f, sk = 0.f;
    #pragma unroll
    for (int r = 0; r < 16; r++) {
        sq += Aq[i*16+r] * Bq[r*64+j];
        sk += Ak[i*16+r] * Bk[r*64+j];
    }
    g_Mq [i*64+j] = sq;
    g_Mkg[i*64+j] = sk * tanhf(1.0f + rand_gate[j]);
}

__global__ void prep_qweff(const float* __restrict__ qw)
{
    int d = blockIdx.x;            /* 0..1023 */
    int c = threadIdx.x;           /* 0..1023 */
    int h = c >> 6, j = c & 63;
    const float* src = qw + (size_t)d*1024 + h*64;
    float acc = 0.f;
    #pragma unroll
    for (int i = 0; i < 64; i++) acc += src[i] * g_Mq[i*64+j];
    g_qweff[(size_t)d*1024 + c] = acc;
}

__global__ void prep_kweff(const float* __restrict__ kw)
{
    int d = blockIdx.x;            /* 0..1023 */
    int c = threadIdx.x;           /* 0..255  */
    int h = c >> 6, j = c & 63;
    const float* src = kw + (size_t)d*256 + h*64;
    float acc = 0.f;
    #pragma unroll
    for (int i = 0; i < 64; i++) acc += src[i] * g_Mkg[i*64+j];
    g_kweff[(size_t)d*256 + c] = acc;
}

/* -------- depthwise 3-tap conv along N + silu(zc)*silu(gate) ------------- */
__global__ void conv_silu(const float* __restrict__ dw_w, const float* __restrict__ dw_b)
{
    int idx = blockIdx.x * blockDim.x + threadIdx.x;    /* NTOK*1024 */
    if (idx >= NTOK*1024) return;
    int d   = idx & 1023;
    int tok = idx >> 10;
    int n   = tok & (SEQ-1);
    const float* zrow = g_zg + (size_t)tok*2048;
    float zc = zrow[d] * dw_w[d*3+1] + dw_b[d];
    if (n > 0)     zc += g_zg[(size_t)(tok-1)*2048 + d] * dw_w[d*3+0];
    if (n < SEQ-1) zc += g_zg[(size_t)(tok+1)*2048 + d] * dw_w[d*3+2];
    float gate = zrow[1024 + d];
    float a = zc   / (1.f + __expf(-zc));
    float b = gate / (1.f + __expf(-gate));
    g_zm[(size_t)tok*1024 + d] = a * b;
}

/* -------- Haar pairing along N (before gather) --------------------------- */
__global__ void haar_kernel()
{
    int idx = blockIdx.x * blockDim.x + threadIdx.x;    /* BATCH*2048*256 */
    if (idx >= BATCH*2048*256) return;
    int d = idx & 255;
    int p = (idx >> 8) & 2047;
    int b = idx >> 19;
    const float* kp = g_kraw + ((size_t)(b*SEQ + 2*p) * 256) + d;
    float a = kp[0], c = kp[256];
    g_khaar[((size_t)(b*SEQ + p)       ) * 256 + d] = 0.5f*(a + c);
    g_khaar[((size_t)(b*SEQ + 2048 + p)) * 256 + d] = 0.5f*(a - c);
}

/* -------- LSH hash: base = qg@base_w, signs -> XOR salts -> bucket ------- */
__global__ void hash_kernel(const float* __restrict__ base_w,
                            const float* __restrict__ rot,
                            const int*   __restrict__ salts)
{
    int tok = blockIdx.x;
    __shared__ float part[128*8];
    const float* qg = g_qk + (size_t)tok * 2048;  /* first 1024 cols = qg */
    float acc[8] = {0,0,0,0,0,0,0,0};
    for (int d = threadIdx.x; d < 1024; d += 128) {
        float x = qg[d];
        #pragma unroll
        for (int c = 0; c < 8; c++) acc[c] += x * base_w[d*8+c];
    }
    #pragma unroll
    for (int c = 0; c < 8; c++) part[threadIdx.x*8+c] = acc[c];
    __syncthreads();
    for (int s = 64; s > 0; s >>= 1) {
        if (threadIdx.x < s)
            #pragma unroll
            for (int c = 0; c < 8; c++)
                part[threadIdx.x*8+c] += part[(threadIdx.x+s)*8+c];
        __syncthreads();
    }
    if (threadIdx.x == 0) {
        float base[8];
        #pragma unroll
        for (int c = 0; c < 8; c++) base[c] = part[c];
        int code = 0;
        #pragma unroll
        for (int r = 0; r < 4; r++) {
            int ph = 0;
            #pragma unroll
            for (int k = 0; k < 8; k++) {
                float sim = 0.f;
                #pragma unroll
                for (int h = 0; h < 8; h++) sim += base[h] * rot[(r*8+h)*8+k];
                if (sim >= 0.f) ph ^= salts[r*8+k];
            }
            code ^= ph;
        }
        g_bucket[tok] = code & (NBKT-1);   /* python-mod == & for pow2, sign bit 0 */
    }
}

/* -------- stable counting sort (matches jnp.argsort stable=True) --------- */
__global__ void sort_kernel()
{
    int b = blockIdx.x;
    __shared__ int cnt[256*32];
    __shared__ int binStart[33];
    int t = threadIdx.x;
    #pragma unroll
    for (int i = 0; i < 32; i++) cnt[t*32+i] = 0;
    __syncthreads();
    const int* bk = g_bucket + b*SEQ;
    int base = t * 16;
    for (int e = 0; e < 16; e++) cnt[t*32 + bk[base+e]]++;
    __syncthreads();
    if (t < 32) {
        int run = 0;
        for (int i = 0; i < 256; i++) { int v = cnt[i*32+t]; cnt[i*32+t] = run; run += v; }
        binStart[t+1] = run;
    }
    __syncthreads();
    if (t == 0) {
        int s = 0;
        for (int i = 0; i < 32; i++) { int tot = binStart[i+1]; binStart[i] = s; s += tot; }
    }
    __syncthreads();
    for (int e = 0; e < 16; e++) {
        int idx = base + e;
        int bb  = bk[idx];
        int pos = binStart[bb] + cnt[t*32+bb]++;
        g_order[b*SEQ + pos] = idx;
    }
}

/* -------- bucketed attention: one block per (bucket-chunk, head, batch) -- */
#define ATTN_SMEM ((128*64 + 128*129) * 4)
__global__ __launch_bounds__(128) void attn_kernel()
{
    extern __shared__ float smem[];
    float* tile = smem;              /* k tile then v tile: [128][64] */
    float* sc   = smem + 128*64;     /* scores/probs: [128][129]      */
    __shared__ int ord[128];

    int c = blockIdx.x, h = blockIdx.y, b = blockIdx.z;
    int t = threadIdx.x;
    ord[t] = g_order[b*SEQ + c*128 + t];
    __syncthreads();
    int hk = h >> 2;
    int n  = ord[t];

    /* load k tile (gathered) */
    {
        const float* kp = g_khaar + ((size_t)(b*SEQ + n)) * 256 + hk*64;
        #pragma unroll
        for (int d4 = 0; d4 < 64; d4 += 4)
            *(float4*)&tile[t*64 + d4] = *(const float4*)&kp[d4];
    }
    /* q row into registers */
    float q[64];
    {
        const float* qp = g_q + ((size_t)(b*SEQ + n)) * 1024 + h*64;
        #pragma unroll
        for (int d4 = 0; d4 < 64; d4 += 4) {
            float4 v4 = *(const float4*)&qp[d4];
            q[d4]=v4.x; q[d4+1]=v4.y; q[d4+2]=v4.z; q[d4+3]=v4.w;
        }
    }
    __syncthreads();

    /* pass 1: scores + max */
    float m = -1e30f;
    const float scale = 0.125f;
    for (int j = 0; j < 128; j++) {
        float s = 0.f;
        #pragma unroll
        for (int d = 0; d < 64; d++) s += q[d] * tile[j*64 + d];
        s *= scale;
        sc[t*129 + j] = s;
        m = fmaxf(m, s);
    }
    float l = 0.f;
    for (int j = 0; j < 128; j++) {
        float p = __expf(sc[t*129 + j] - m);
        sc[t*129 + j] = p;
        l += p;
    }
    __syncthreads();      /* everyone done reading k tile */

    /* load v tile over k tile */
    {
        const float* vp = g_v + ((size_t)(b*SEQ + n)) * 256 + hk*64;
        #pragma unroll
        for (int d4 = 0; d4 < 64; d4 += 4)
            *(float4*)&tile[t*64 + d4] = *(const float4*)&vp[d4];
    }
    __syncthreads();

    /* pass 2: P @ V */
    float acc[64];
    #pragma unroll
    for (int d = 0; d < 64; d++) acc[d] = 0.f;
    for (int j = 0; j < 128; j++) {
        float p = sc[t*129 + j];
        #pragma unroll
        for (int d = 0; d < 64; d++) acc[d] += p * tile[j*64 + d];
    }
    float rl = 1.f / l;
    float* op = g_o + ((size_t)(b*SEQ + n)) * 1024 + h*64;
    #pragma unroll
    for (int d4 = 0; d4 < 64; d4 += 4) {
        float4 v4 = make_float4(acc[d4]*rl, acc[d4+1]*rl, acc[d4+2]*rl, acc[d4+3]*rl);
        *(float4*)&op[d4] = v4;
    }
}

/* ------------------------------ driver ----------------------------------- */
extern "C" void kernel_launch(void* const* d_in, const int* in_sizes, int n_in,
                              void* d_out, int out_size)
{
    const float* x         = (const float*)d_in[0];
    const float* ge_inp_w  = (const float*)d_in[1];
    const float* dw_w      = (const float*)d_in[2];
    const float* dw_b      = (const float*)d_in[3];
    const float* ge_out_w  = (const float*)d_in[4];
    const float* q_w       = (const float*)d_in[5];
    const float* k_w       = (const float*)d_in[6];
    const float* v_w       = (const float*)d_in[7];
    const float* Aq        = (const float*)d_in[8];
    const float* Bq        = (const float*)d_in[9];
    const float* Ak        = (const float*)d_in[10];
    const float* Bk        = (const float*)d_in[11];
    const float* rand_gate = (const float*)d_in[12];
    const float* base_w    = (const float*)d_in[13];
    const float* rot       = (const float*)d_in[14];
    /* d_in[15] = u : unused by reference */
    const float* o_w       = (const float*)d_in[16];
    const int*   salts     = (const int*)  d_in[17];

    float *zg, *zm, *qk, *q, *kraw, *v, *o, *qweff, *kweff;
    cudaGetSymbolAddress((void**)&zg,    g_zg);
    cudaGetSymbolAddress((void**)&zm,    g_zm);
    cudaGetSymbolAddress((void**)&qk,    g_qk);
    cudaGetSymbolAddress((void**)&q,     g_q);
    cudaGetSymbolAddress((void**)&kraw,  g_kraw);
    cudaGetSymbolAddress((void**)&v,     g_v);
    cudaGetSymbolAddress((void**)&o,     g_o);
    cudaGetSymbolAddress((void**)&qweff, g_qweff);
    cudaGetSymbolAddress((void**)&kweff, g_kweff);

    /* fold low-rank + gate into weights */
    prep_M<<<64, 64>>>(Aq, Bq, Ak, Bk, rand_gate);
    prep_qweff<<<1024, 1024>>>(q_w);
    prep_kweff<<<1024, 256>>>(k_w);

    /* zg = x @ ge_inp_w   [8192,2048] */
    sgemm128<<<dim3(16, 64), 256>>>(x, ge_inp_w, zg, 1024, 1024, 2048, 2048);
    /* v = x @ v_w         [8192,256]  */
    sgemm128<<<dim3(2, 64), 256>>>(x, v_w, v, 1024, 1024, 256, 256);
    /* conv + silu gates */
    conv_silu<<<(NTOK*1024)/256, 256>>>(dw_w, dw_b);
    /* qk = zm @ ge_out_w  [8192,2048] */
    sgemm128<<<dim3(16, 64), 256>>>(zm, ge_out_w, qk, 1024, 1024, 2048, 2048);
    /* q = qg @ q_w_eff    [8192,1024] */
    sgemm128<<<dim3(8, 64), 256>>>(qk, qweff, q, 1024, 2048, 1024, 1024);
    /* kraw = kg @ k_w_eff [8192,256]  */
    sgemm128<<<dim3(2, 64), 256>>>(qk + 1024, kweff, kraw, 1024, 2048, 256, 256);
    /* haar pairing */
    haar_kernel<<<(BATCH*2048*256)/256, 256>>>();
    /* LSH bucket ids */
    hash_kernel<<<NTOK, 128>>>(base_w, rot, salts);
    /* stable counting sort per batch */
    sort_kernel<<<BATCH, 256>>>();
    /* bucketed attention */
    cudaFuncSetAttribute(attn_kernel, cudaFuncAttributeMaxDynamicSharedMemorySize, ATTN_SMEM);
    attn_kernel<<<dim3(NBKT, NHEAD, BATCH), 128, ATTN_SMEM>>>();
    /* out = o @ o_w       [8192,1024] */
    sgemm128<<<dim3(8, 64), 256>>>(o, o_w, (float*)d_out, 1024, 1024, 1024, 1024);
}

// round 11
// speedup vs baseline: 1.4821x; 1.4821x over previous
#include <cuda_runtime.h>
#include <cuda_bf16.h>
#include <math.h>

#define BATCH   2
#define SEQ     4096
#define NTOK    (BATCH*SEQ)     /* 8192 */
#define NHEAD   16
#define DHEAD   64
#define NBKT    32
#define BUCKET  128

typedef __nv_bfloat16 bf16;

/* ---------------- scratch (device globals; no allocation allowed) -------- */
__device__ float g_zg   [NTOK*2048];   /* z | gate (fp32)     */
__device__ float g_qk   [NTOK*2048];   /* qg | kg (fp32, for hash) */
__device__ float g_q    [NTOK*1024];
__device__ float g_kraw [NTOK*256];
__device__ float g_khaar[NTOK*256];
__device__ float g_v    [NTOK*256];
__device__ float g_Mq   [64*64];
__device__ float g_Mkg  [64*64];
__device__ int   g_bucket[NTOK];
__device__ int   g_order [NTOK];

/* bf16 3-way splits of GEMM operands */
__device__ bf16 g_xh [NTOK*1024], g_xm [NTOK*1024], g_xl [NTOK*1024];
__device__ bf16 g_zmh[NTOK*1024], g_zmm[NTOK*1024], g_zml[NTOK*1024];
__device__ bf16 g_qkh[NTOK*2048], g_qkm[NTOK*2048], g_qkl[NTOK*2048];
__device__ bf16 g_oh [NTOK*1024], g_om [NTOK*1024], g_ol [NTOK*1024];
/* transposed weights [N,K] bf16 splits */
__device__ bf16 g_wiTh[2048*1024], g_wiTm[2048*1024], g_wiTl[2048*1024];
__device__ bf16 g_woTh[2048*1024], g_woTm[2048*1024], g_woTl[2048*1024];
__device__ bf16 g_qwTh[1024*1024], g_qwTm[1024*1024], g_qwTl[1024*1024];
__device__ bf16 g_kwTh[256*1024],  g_kwTm[256*1024],  g_kwTl[256*1024];
__device__ bf16 g_vwTh[256*1024],  g_vwTm[256*1024],  g_vwTl[256*1024];
__device__ bf16 g_owTh[1024*1024], g_owTm[1024*1024], g_owTl[1024*1024];

/* ---------------- helpers ------------------------------------------------ */
__device__ __forceinline__ unsigned smem_u32(const void* p) {
    unsigned r;
    asm("{ .reg .u64 t; cvta.to.shared.u64 t, %1; cvt.u32.u64 %0, t; }" : "=r"(r) : "l"(p));
    return r;
}
__device__ __forceinline__ void split3f(float x, bf16& h, bf16& m, bf16& l) {
    h = __float2bfloat16(x);
    float r1 = x - __bfloat162float(h);
    m = __float2bfloat16(r1);
    float r2 = r1 - __bfloat162float(m);
    l = __float2bfloat16(r2);
}
__device__ __forceinline__ void ldsm_x4(unsigned* r, unsigned addr) {
    asm volatile("ldmatrix.sync.aligned.m8n8.x4.shared.b16 {%0,%1,%2,%3}, [%4];"
        : "=r"(r[0]), "=r"(r[1]), "=r"(r[2]), "=r"(r[3]) : "r"(addr));
}
__device__ __forceinline__ void ldsm_x2(unsigned* r, unsigned addr) {
    asm volatile("ldmatrix.sync.aligned.m8n8.x2.shared.b16 {%0,%1}, [%2];"
        : "=r"(r[0]), "=r"(r[1]) : "r"(addr));
}
__device__ __forceinline__ void mma16816(float* c, const unsigned* a, const unsigned* b) {
    asm volatile("mma.sync.aligned.m16n8k16.row.col.f32.bf16.bf16.f32 "
        "{%0,%1,%2,%3}, {%4,%5,%6,%7}, {%8,%9}, {%0,%1,%2,%3};"
        : "+f"(c[0]), "+f"(c[1]), "+f"(c[2]), "+f"(c[3])
        : "r"(a[0]), "r"(a[1]), "r"(a[2]), "r"(a[3]), "r"(b[0]), "r"(b[1]));
}

/* single shared-memory symbol for all dynamic-smem kernels */
extern __shared__ char smem_raw[];

/* ========== HMMA bf16-split GEMM: C[M,N] = A[M,K] @ B^T  ================== */
/* A*: [M,K] bf16 splits; B*: [N,K] bf16 splits (both row-major).
   CTA tile 128x128, BK=32, 8 warps (warp tile 64x32), mma.m16n8k16.
   smem: per split s: A tile at s*5120, B tile at (3+s)*5120 (bf16 elems),
   row pitch 40 bf16 (80 B) => ldmatrix conflict-free.                     */
#define PITCH 40
#define TILE_E (128*PITCH)            /* bf16 elements per tile = 5120 */
#define TCG_SMEM (6*TILE_E*2)         /* 61440 bytes */
__global__ __launch_bounds__(256) void tc_gemm(
    const bf16* __restrict__ Ah, const bf16* __restrict__ Am, const bf16* __restrict__ Al,
    const bf16* __restrict__ Bh, const bf16* __restrict__ Bm, const bf16* __restrict__ Bl,
    float* __restrict__ C, int K, int lda, int ldc, int terms)
{
    bf16* sm = (bf16*)smem_raw;
    unsigned sbase = smem_u32(sm);
    int tid = threadIdx.x, wid = tid >> 5, lid = tid & 31;
    int m0 = blockIdx.y * 128, n0 = blockIdx.x * 128;
    int wm = (wid >> 2) * 64, wn = (wid & 3) * 32;

    const bf16* Asp[3] = {Ah, Am, Al};
    const bf16* Bsp[3] = {Bh, Bm, Bl};
    const int nsplit = (terms == 6) ? 3 : 2;
    const int ta[6]  = {0,0,1,0,2,1};   /* hh,hm,mh,hl,lh,mm */
    const int tbx[6] = {0,1,0,2,0,1};

    float c[4][4][4];
    #pragma unroll
    for (int i = 0; i < 4; i++)
        #pragma unroll
        for (int j = 0; j < 4; j++)
            #pragma unroll
            for (int e = 0; e < 4; e++) c[i][j][e] = 0.f;

    /* ldmatrix lane addressing */
    int arow = lid & 15, ahalf = lid >> 4;        /* A: x4 */
    int brow = lid & 7,  bhalf = (lid >> 3) & 1;  /* B: x2 */

    for (int k0 = 0; k0 < K; k0 += 32) {
        /* stage nsplit A and B subtiles: 128 rows x 32 bf16 each */
        for (int s = 0; s < nsplit; s++) {
            const bf16* srcA = Asp[s] + (size_t)m0 * lda + k0;
            const bf16* srcB = Bsp[s] + (size_t)n0 * 1024 + k0;
            bf16* dstA = sm + s * TILE_E;
            bf16* dstB = sm + (3 + s) * TILE_E;
            #pragma unroll
            for (int i = 0; i < 2; i++) {
                int idx = i * 256 + tid;
                int row = idx >> 2, cc = idx & 3;
                *(uint4*)(dstA + row * PITCH + cc * 8) =
                    *(const uint4*)(srcA + (size_t)row * lda + cc * 8);
                *(uint4*)(dstB + row * PITCH + cc * 8) =
                    *(const uint4*)(srcB + (size_t)row * 1024 + cc * 8);
            }
        }
        __syncthreads();

        for (int t = 0; t < terms; t++) {
            unsigned abase = sbase + ta[t]  * TILE_E * 2;
            unsigned bbase = sbase + (3 + tbx[t]) * TILE_E * 2;
            #pragma unroll
            for (int k16 = 0; k16 < 32; k16 += 16) {
                unsigned af[4][4], bf[4][2];
                #pragma unroll
                for (int ma = 0; ma < 4; ma++)
                    ldsm_x4(af[ma], abase +
                        ((wm + ma*16 + arow) * PITCH + k16 + ahalf*8) * 2);
                #pragma unroll
                for (int na = 0; na < 4; na++)
                    ldsm_x2(bf[na], bbase +
                        ((wn + na*8 + brow) * PITCH + k16 + bhalf*8) * 2);
                #pragma unroll
                for (int ma = 0; ma < 4; ma++)
                    #pragma unroll
                    for (int na = 0; na < 4; na++)
                        mma16816(c[ma][na], af[ma], bf[na]);
            }
        }
        __syncthreads();
    }

    /* epilogue: d0:(g, 2t) d1:(g, 2t+1) d2:(g+8, 2t) d3:(g+8, 2t+1) */
    int g = lid >> 2, tg = lid & 3;
    #pragma unroll
    for (int ma = 0; ma < 4; ma++) {
        #pragma unroll
        for (int na = 0; na < 4; na++) {
            int row = m0 + wm + ma*16 + g;
            int col = n0 + wn + na*8 + tg*2;
            *(float2*)&C[(size_t)row * ldc + col] = make_float2(c[ma][na][0], c[ma][na][1]);
            *(float2*)&C[(size_t)(row + 8) * ldc + col] = make_float2(c[ma][na][2], c[ma][na][3]);
        }
    }
}

/* -------- elementwise fp32 -> 3x bf16 split ------------------------------ */
__global__ void split3_arr(const float* __restrict__ src, bf16* h, bf16* m, bf16* l, int count)
{
    int i = blockIdx.x * blockDim.x + threadIdx.x;
    if (i >= count) return;
    bf16 a, b, c; split3f(src[i], a, b, c);
    h[i] = a; m[i] = b; l[i] = c;
}

/* -------- transpose + split: W[K,N] fp32 -> Wt[N,K] bf16 x3 -------------- */
__global__ void tsplit(const float* __restrict__ W, bf16* h, bf16* m, bf16* l, int K, int N)
{
    int idx = blockIdx.x * blockDim.x + threadIdx.x;
    if (idx >= N * K) return;
    int n = idx / K, k = idx - n * K;
    bf16 a, b, c; split3f(W[(size_t)k * N + n], a, b, c);
    h[idx] = a; m[idx] = b; l[idx] = c;
}

/* -------- fold low-rank projections (+ tanh gate for k) into weights ----- */
__global__ void prep_M(const float* __restrict__ Aq, const float* __restrict__ Bq,
                       const float* __restrict__ Ak, const float* __restrict__ Bk,
                       const float* __restrict__ rand_gate)
{
    int i = blockIdx.x, j = threadIdx.x;
    float sq = 0.f, sk = 0.f;
    #pragma unroll
    for (int r = 0; r < 16; r++) {
        sq += Aq[i*16+r] * Bq[r*64+j];
        sk += Ak[i*16+r] * Bk[r*64+j];
    }
    g_Mq [i*64+j] = sq;
    g_Mkg[i*64+j] = sk * tanhf(1.0f + rand_gate[j]);
}

/* folded q weight, transposed [N=1024, K=1024], bf16 x3 */
__global__ void prep_qweffT(const float* __restrict__ qw)
{
    int d = blockIdx.x;            /* K index 0..1023 */
    int c = threadIdx.x;           /* N index 0..1023 */
    int h = c >> 6, j = c & 63;
    const float* src = qw + (size_t)d*1024 + h*64;
    float acc = 0.f;
    #pragma unroll
    for (int i = 0; i < 64; i++) acc += src[i] * g_Mq[i*64+j];
    bf16 a, b, cc; split3f(acc, a, b, cc);
    size_t o = (size_t)c*1024 + d;
    g_qwTh[o] = a; g_qwTm[o] = b; g_qwTl[o] = cc;
}

__global__ void prep_kweffT(const float* __restrict__ kw)
{
    int d = blockIdx.x;            /* K 0..1023 */
    int c = threadIdx.x;           /* N 0..255  */
    int h = c >> 6, j = c & 63;
    const float* src = kw + (size_t)d*256 + h*64;
    float acc = 0.f;
    #pragma unroll
    for (int i = 0; i < 64; i++) acc += src[i] * g_Mkg[i*64+j];
    bf16 a, b, cc; split3f(acc, a, b, cc);
    size_t o = (size_t)c*1024 + d;
    g_kwTh[o] = a; g_kwTm[o] = b; g_kwTl[o] = cc;
}

/* -------- depthwise conv + silu*silu -> zm splits ------------------------ */
__global__ void conv_silu(const float* __restrict__ dw_w, const float* __restrict__ dw_b)
{
    int idx = blockIdx.x * blockDim.x + threadIdx.x;
    if (idx >= NTOK*1024) return;
    int d   = idx & 1023;
    int tok = idx >> 10;
    int n   = tok & (SEQ-1);
    const float* zrow = g_zg + (size_t)tok*2048;
    float zc = zrow[d] * dw_w[d*3+1] + dw_b[d];
    if (n > 0)     zc += g_zg[(size_t)(tok-1)*2048 + d] * dw_w[d*3+0];
    if (n < SEQ-1) zc += g_zg[(size_t)(tok+1)*2048 + d] * dw_w[d*3+2];
    float gate = zrow[1024 + d];
    float a = zc   / (1.f + __expf(-zc));
    float b = gate / (1.f + __expf(-gate));
    bf16 h, m, l; split3f(a * b, h, m, l);
    size_t o = (size_t)tok*1024 + d;
    g_zmh[o] = h; g_zmm[o] = m; g_zml[o] = l;
}

/* -------- Haar pairing along N ------------------------------------------- */
__global__ void haar_kernel()
{
    int idx = blockIdx.x * blockDim.x + threadIdx.x;
    if (idx >= BATCH*2048*256) return;
    int d = idx & 255;
    int p = (idx >> 8) & 2047;
    int b = idx >> 19;
    const float* kp = g_kraw + ((size_t)(b*SEQ + 2*p) * 256) + d;
    float a = kp[0], c = kp[256];
    g_khaar[((size_t)(b*SEQ + p)       ) * 256 + d] = 0.5f*(a + c);
    g_khaar[((size_t)(b*SEQ + 2048 + p)) * 256 + d] = 0.5f*(a - c);
}

/* -------- LSH hash ------------------------------------------------------- */
__global__ void hash_kernel(const float* __restrict__ base_w,
                            const float* __restrict__ rot,
                            const int*   __restrict__ salts)
{
    int tok = blockIdx.x;
    __shared__ float part[128*8];
    const float* qg = g_qk + (size_t)tok * 2048;
    float acc[8] = {0,0,0,0,0,0,0,0};
    for (int d = threadIdx.x; d < 1024; d += 128) {
        float x = qg[d];
        #pragma unroll
        for (int c = 0; c < 8; c++) acc[c] += x * base_w[d*8+c];
    }
    #pragma unroll
    for (int c = 0; c < 8; c++) part[threadIdx.x*8+c] = acc[c];
    __syncthreads();
    for (int s = 64; s > 0; s >>= 1) {
        if (threadIdx.x < s)
            #pragma unroll
            for (int c = 0; c < 8; c++)
                part[threadIdx.x*8+c] += part[(threadIdx.x+s)*8+c];
        __syncthreads();
    }
    if (threadIdx.x == 0) {
        float base[8];
        #pragma unroll
        for (int c = 0; c < 8; c++) base[c] = part[c];
        int code = 0;
        #pragma unroll
        for (int r = 0; r < 4; r++) {
            int ph = 0;
            #pragma unroll
            for (int k = 0; k < 8; k++) {
                float sim = 0.f;
                #pragma unroll
                for (int h = 0; h < 8; h++) sim += base[h] * rot[(r*8+h)*8+k];
                if (sim >= 0.f) ph ^= salts[r*8+k];
            }
            code ^= ph;
        }
        g_bucket[tok] = code & (NBKT-1);
    }
}

/* -------- stable counting sort ------------------------------------------- */
__global__ void sort_kernel()
{
    int b = blockIdx.x;
    __shared__ int cnt[256*32];
    __shared__ int binStart[33];
    int t = threadIdx.x;
    #pragma unroll
    for (int i = 0; i < 32; i++) cnt[t*32+i] = 0;
    __syncthreads();
    const int* bk = g_bucket + b*SEQ;
    int base = t * 16;
    for (int e = 0; e < 16; e++) cnt[t*32 + bk[base+e]]++;
    __syncthreads();
    if (t < 32) {
        int run = 0;
        for (int i = 0; i < 256; i++) { int v = cnt[i*32+t]; cnt[i*32+t] = run; run += v; }
        binStart[t+1] = run;
    }
    __syncthreads();
    if (t == 0) {
        int s = 0;
        for (int i = 0; i < 32; i++) { int tot = binStart[i+1]; binStart[i] = s; s += tot; }
    }
    __syncthreads();
    for (int e = 0; e < 16; e++) {
        int idx = base + e;
        int bb  = bk[idx];
        int pos = binStart[bb] + cnt[t*32+bb]++;
        g_order[b*SEQ + pos] = idx;
    }
}

/* -------- bucketed attention (writes o splits directly) ------------------ */
#define ATTN_SMEM ((128*64 + 128*129) * 4)
__global__ __launch_bounds__(128) void attn_kernel()
{
    float* smem = (float*)smem_raw;
    float* tile = smem;
    float* sc   = smem + 128*64;
    __shared__ int ord[128];

    int c = blockIdx.x, h = blockIdx.y, b = blockIdx.z;
    int t = threadIdx.x;
    ord[t] = g_order[b*SEQ + c*128 + t];
    __syncthreads();
    int hk = h >> 2;
    int n  = ord[t];

    {
        const float* kp = g_khaar + ((size_t)(b*SEQ + n)) * 256 + hk*64;
        #pragma unroll
        for (int d4 = 0; d4 < 64; d4 += 4)
            *(float4*)&tile[t*64 + d4] = *(const float4*)&kp[d4];
    }
    float q[64];
    {
        const float* qp = g_q + ((size_t)(b*SEQ + n)) * 1024 + h*64;
        #pragma unroll
        for (int d4 = 0; d4 < 64; d4 += 4) {
            float4 v4 = *(const float4*)&qp[d4];
            q[d4]=v4.x; q[d4+1]=v4.y; q[d4+2]=v4.z; q[d4+3]=v4.w;
        }
    }
    __syncthreads();

    float m = -1e30f;
    const float scale = 0.125f;
    for (int j = 0; j < 128; j++) {
        float s = 0.f;
        #pragma unroll
        for (int d = 0; d < 64; d++) s += q[d] * tile[j*64 + d];
        s *= scale;
        sc[t*129 + j] = s;
        m = fmaxf(m, s);
    }
    float l = 0.f;
    for (int j = 0; j < 128; j++) {
        float p = __expf(sc[t*129 + j] - m);
        sc[t*129 + j] = p;
        l += p;
    }
    __syncthreads();

    {
        const float* vp = g_v + ((size_t)(b*SEQ + n)) * 256 + hk*64;
        #pragma unroll
        for (int d4 = 0; d4 < 64; d4 += 4)
            *(float4*)&tile[t*64 + d4] = *(const float4*)&vp[d4];
    }
    __syncthreads();

    float acc[64];
    #pragma unroll
    for (int d = 0; d < 64; d++) acc[d] = 0.f;
    for (int j = 0; j < 128; j++) {
        float p = sc[t*129 + j];
        #pragma unroll
        for (int d = 0; d < 64; d++) acc[d] += p * tile[j*64 + d];
    }
    float rl = 1.f / l;
    size_t obase = ((size_t)(b*SEQ + n)) * 1024 + h*64;
    #pragma unroll
    for (int d2 = 0; d2 < 64; d2 += 2) {
        float v0 = acc[d2]*rl, v1 = acc[d2+1]*rl;
        bf16 h0,m0,l0,h1,m1,l1;
        split3f(v0, h0, m0, l0); split3f(v1, h1, m1, l1);
        *(__nv_bfloat162*)&g_oh[obase + d2] = __nv_bfloat162(h0, h1);
        *(__nv_bfloat162*)&g_om[obase + d2] = __nv_bfloat162(m0, m1);
        *(__nv_bfloat162*)&g_ol[obase + d2] = __nv_bfloat162(l0, l1);
    }
}

/* ------------------------------ driver ----------------------------------- */
extern "C" void kernel_launch(void* const* d_in, const int* in_sizes, int n_in,
                              void* d_out, int out_size)
{
    const float* x         = (const float*)d_in[0];
    const float* ge_inp_w  = (const float*)d_in[1];
    const float* dw_w      = (const float*)d_in[2];
    const float* dw_b      = (const float*)d_in[3];
    const float* ge_out_w  = (const float*)d_in[4];
    const float* q_w       = (const float*)d_in[5];
    const float* k_w       = (const float*)d_in[6];
    const float* v_w       = (const float*)d_in[7];
    const float* Aq        = (const float*)d_in[8];
    const float* Bq        = (const float*)d_in[9];
    const float* Ak        = (const float*)d_in[10];
    const float* Bk        = (const float*)d_in[11];
    const float* rand_gate = (const float*)d_in[12];
    const float* base_w    = (const float*)d_in[13];
    const float* rot       = (const float*)d_in[14];
    const float* o_w       = (const float*)d_in[16];
    const int*   salts     = (const int*)  d_in[17];

    float *zg, *qk, *qf, *kraw, *vf;
    cudaGetSymbolAddress((void**)&zg,   g_zg);
    cudaGetSymbolAddress((void**)&qk,   g_qk);
    cudaGetSymbolAddress((void**)&qf,   g_q);
    cudaGetSymbolAddress((void**)&kraw, g_kraw);
    cudaGetSymbolAddress((void**)&vf,   g_v);
    bf16 *xh,*xm,*xl,*zmh,*zmm,*zml,*qkh,*qkm,*qkl,*oh,*om,*ol;
    bf16 *wiTh,*wiTm,*wiTl,*woTh,*woTm,*woTl,*qwTh,*qwTm,*qwTl;
    bf16 *kwTh,*kwTm,*kwTl,*vwTh,*vwTm,*vwTl,*owTh,*owTm,*owTl;
    cudaGetSymbolAddress((void**)&xh, g_xh);   cudaGetSymbolAddress((void**)&xm, g_xm);
    cudaGetSymbolAddress((void**)&xl, g_xl);
    cudaGetSymbolAddress((void**)&zmh, g_zmh); cudaGetSymbolAddress((void**)&zmm, g_zmm);
    cudaGetSymbolAddress((void**)&zml, g_zml);
    cudaGetSymbolAddress((void**)&qkh, g_qkh); cudaGetSymbolAddress((void**)&qkm, g_qkm);
    cudaGetSymbolAddress((void**)&qkl, g_qkl);
    cudaGetSymbolAddress((void**)&oh, g_oh);   cudaGetSymbolAddress((void**)&om, g_om);
    cudaGetSymbolAddress((void**)&ol, g_ol);
    cudaGetSymbolAddress((void**)&wiTh, g_wiTh); cudaGetSymbolAddress((void**)&wiTm, g_wiTm);
    cudaGetSymbolAddress((void**)&wiTl, g_wiTl);
    cudaGetSymbolAddress((void**)&woTh, g_woTh); cudaGetSymbolAddress((void**)&woTm, g_woTm);
    cudaGetSymbolAddress((void**)&woTl, g_woTl);
    cudaGetSymbolAddress((void**)&qwTh, g_qwTh); cudaGetSymbolAddress((void**)&qwTm, g_qwTm);
    cudaGetSymbolAddress((void**)&qwTl, g_qwTl);
    cudaGetSymbolAddress((void**)&kwTh, g_kwTh); cudaGetSymbolAddress((void**)&kwTm, g_kwTm);
    cudaGetSymbolAddress((void**)&kwTl, g_kwTl);
    cudaGetSymbolAddress((void**)&vwTh, g_vwTh); cudaGetSymbolAddress((void**)&vwTm, g_vwTm);
    cudaGetSymbolAddress((void**)&vwTl, g_vwTl);
    cudaGetSymbolAddress((void**)&owTh, g_owTh); cudaGetSymbolAddress((void**)&owTm, g_owTm);
    cudaGetSymbolAddress((void**)&owTl, g_owTl);

    cudaFuncSetAttribute(tc_gemm, cudaFuncAttributeMaxDynamicSharedMemorySize, TCG_SMEM);
    cudaFuncSetAttribute(attn_kernel, cudaFuncAttributeMaxDynamicSharedMemorySize, ATTN_SMEM);

    /* weight prep: folds, transposes, bf16 splits */
    prep_M<<<64, 64>>>(Aq, Bq, Ak, Bk, rand_gate);
    prep_qweffT<<<1024, 1024>>>(q_w);
    prep_kweffT<<<1024, 256>>>(k_w);
    split3_arr<<<(NTOK*1024+255)/256, 256>>>(x, xh, xm, xl, NTOK*1024);
    tsplit<<<(2048*1024+255)/256, 256>>>(ge_inp_w, wiTh, wiTm, wiTl, 1024, 2048);
    tsplit<<<(2048*1024+255)/256, 256>>>(ge_out_w, woTh, woTm, woTl, 1024, 2048);
    tsplit<<<(256*1024+255)/256, 256>>>(v_w, vwTh, vwTm, vwTl, 1024, 256);
    tsplit<<<(1024*1024+255)/256, 256>>>(o_w, owTh, owTm, owTl, 1024, 1024);

    /* zg = x @ ge_inp_w  (hash-critical chain: 6 terms) */
    tc_gemm<<<dim3(16,64), 256, TCG_SMEM>>>(xh,xm,xl, wiTh,wiTm,wiTl, zg, 1024, 1024, 2048, 6);
    /* v = x @ v_w */
    tc_gemm<<<dim3(2,64), 256, TCG_SMEM>>>(xh,xm,xl, vwTh,vwTm,vwTl, vf, 1024, 1024, 256, 3);
    /* conv + silu -> zm splits */
    conv_silu<<<(NTOK*1024)/256, 256>>>(dw_w, dw_b);
    /* qk = zm @ ge_out_w (hash-critical: 6 terms, fp32 out for hash) */
    tc_gemm<<<dim3(16,64), 256, TCG_SMEM>>>(zmh,zmm,zml, woTh,woTm,woTl, qk, 1024, 1024, 2048, 6);
    split3_arr<<<(NTOK*2048+255)/256, 256>>>(qk, qkh, qkm, qkl, NTOK*2048);
    /* hash + sort */
    hash_kernel<<<NTOK, 128>>>(base_w, rot, salts);
    sort_kernel<<<BATCH, 256>>>();
    /* q = qg @ qweff */
    tc_gemm<<<dim3(8,64), 256, TCG_SMEM>>>(qkh,qkm,qkl, qwTh,qwTm,qwTl, qf, 1024, 2048, 1024, 3);
    /* kraw = kg @ kweff */
    tc_gemm<<<dim3(2,64), 256, TCG_SMEM>>>(qkh+1024,qkm+1024,qkl+1024, kwTh,kwTm,kwTl,
                                           kraw, 1024, 2048, 256, 3);
    haar_kernel<<<(BATCH*2048*256)/256, 256>>>();
    attn_kernel<<<dim3(NBKT, NHEAD, BATCH), 128, ATTN_SMEM>>>();
    /* out = o @ o_w */
    tc_gemm<<<dim3(8,64), 256, TCG_SMEM>>>(oh,om,ol, owTh,owTm,owTl,
                                           (float*)d_out, 1024, 1024, 1024, 3);
}